// round 16
// baseline (speedup 1.0000x reference)
#include <cuda_runtime.h>
#include <math.h>
#include <float.h>

#define BB 1024
#define TT 512
#define KK 48
#define NEGV (-10000.0f)
#define TAG_START 46
#define TAG_STOP 47
#define NBAT 8                      // batches per CTA: 4 groups x 2
#define MAIN_THREADS 384            // 4 groups x 96 (3 aligned warps each)

// ---- device scratch (no allocations allowed) ----
__device__ int   g_bestlast[BB];
__device__ float g_v[BB * TT * KK];   // per-step Viterbi value vectors (100 MB)

// f32x2 packed helpers (sm_103a; add/mul/fma only)
#define F32X2_FMA(d, a, b, c) \
    asm("fma.rn.f32x2 %0, %1, %2, %3;" : "=l"(d) : "l"(a), "l"(b), "l"(c))
#define F32X2_UNPACK(lo, hi, x) \
    asm("mov.b64 {%0, %1}, %2;" : "=f"(lo), "=f"(hi) : "l"(x))
#define F32X2_PACK(d, lo, hi) \
    asm("mov.b64 %0, {%1, %2};" : "=l"(d) : "f"(lo), "f"(hi))

// ============================================================
// Fused kernel, TWO ROWS PER THREAD (crossbar-bound fix):
// thread (i,h) of a batch loads e/v slice [24h,24h+24) ONCE and computes
// next-rows nx=i and nx=i+24 with two register M/t rows. This halves
// smem crossbar wavefronts per output row — the measured bottleneck
// (1152 wf/step model matched R5/R12 within 2%).
// Group = 96 threads (3 aligned warps) = 2 batches; per-group named bar.
// h==1 threads keep no recurrence state: compute partials, shfl to h==0.
// Viterbi numerics exact (same FADD inputs, max order-free); paths
// recomputed bit-exact in backtrack (unchanged R5 scheme).
// ============================================================
__global__ void __launch_bounds__(MAIN_THREADS)
crf_main_kernel(const float* __restrict__ feats,
                const float* __restrict__ trans,
                const int* __restrict__ tags,
                float* __restrict__ out) {
    __shared__ float trans_sh[KK * 49];                 // masked, pitch 49
    __shared__ __align__(16) float e_sh[2][NBAT][KK];   // double buffered
    __shared__ __align__(16) float v_sh[2][NBAT][KK];
    __shared__ int tag_sh[NBAT][TT];

    int tid = threadIdx.x;
    int grp = tid / 96;
    int j   = tid - grp * 96;
    int ab  = j / 48;
    int q   = j - ab * 48;
    int i   = q >> 1;            // 0..23
    int h   = q & 1;             // prev half
    int base = h * 24;
    int s   = grp * 2 + ab;      // batch slot 0..7
    int b   = blockIdx.x * NBAT + s;
    int nx1 = i, nx2 = i + 24;   // the two owned next-rows
    int barid = grp + 1;

    // masked transitions: trans[next, prev]; never INTO start, never OUT of stop
    for (int x = tid; x < KK * KK; x += MAIN_THREADS) {
        int rr = x / KK, cc = x - rr * KK;
        float tv = trans[x];
        if (rr == TAG_START || cc == TAG_STOP) tv = NEGV;
        trans_sh[rr * 49 + cc] = tv;
    }
    for (int x = tid; x < NBAT * TT; x += MAIN_THREADS)
        ((int*)tag_sh)[x] = tags[(size_t)blockIdx.x * NBAT * TT + x];
    __syncthreads();

    // register rows: packed exp(trans) for FMA2; scalar trans for Viterbi
    unsigned long long Ms2a[12], Ms2b[12];
    float tsa[24], tsb[24];
#pragma unroll
    for (int p = 0; p < 24; p++) {
        tsa[p] = trans_sh[nx1 * 49 + base + p];
        tsb[p] = trans_sh[nx2 * 49 + base + p];
    }
#pragma unroll
    for (int jj = 0; jj < 12; jj++) {
        float a0 = tsa[2 * jj],     a1 = tsa[2 * jj + 1];
        float b0 = tsb[2 * jj],     b1 = tsb[2 * jj + 1];
        float Ma0 = (a0 <= -9000.f) ? 0.f : __expf(a0);
        float Ma1 = (a1 <= -9000.f) ? 0.f : __expf(a1);
        float Mb0 = (b0 <= -9000.f) ? 0.f : __expf(b0);
        float Mb1 = (b1 <= -9000.f) ? 0.f : __expf(b1);
        F32X2_PACK(Ms2a[jj], Ma0, Ma1);
        F32X2_PACK(Ms2b[jj], Mb0, Mb1);
    }

    // recurrence state (h==0 threads only use it)
    float a1s = NEGV;                          // nx1 in 0..23, never START
    float a2s = (nx2 == TAG_START) ? 0.f : NEGV;
    float v1s = a1s, v2s = a2s;
    float m = 0.f, gold = 0.f;
    int pt = TAG_START;

    const float* fp = feats + (size_t)b * TT * KK;
    float* vout = g_v + (size_t)b * TT * KK;
    float e1c = 0.f, e2c = 0.f;
    if (h == 0) { e1c = fp[nx1]; e2c = fp[nx2]; }

    for (int t = 0; t < TT; t++) {
        int par = t & 1;
        float e1n = 0.f, e2n = 0.f;
        if (h == 0) {
            if (t + 1 < TT) {
                e1n = fp[(size_t)(t + 1) * KK + nx1];
                e2n = fp[(size_t)(t + 1) * KK + nx2];
            }
            e_sh[par][s][nx1] = __expf(a1s - m);
            e_sh[par][s][nx2] = __expf(a2s - m);
            v_sh[par][s][nx1] = v1s;
            v_sh[par][s][nx2] = v2s;
            vout[(size_t)t * KK + nx1] = v1s;
            vout[(size_t)t * KK + nx2] = v2s;
        }
        asm volatile("bar.sync %0, 96;" :: "r"(barid));

        if (h == 0) {
            int tg = tag_sh[s][t];
            if (nx1 == tg) gold += e1c + trans_sh[tg * 49 + pt];
            if (nx2 == tg) gold += e2c + trans_sh[tg * 49 + pt];
            pt = tg;
        }

        const ulonglong2* ep = (const ulonglong2*)&e_sh[par][s][base];
        const float4*     vp = (const float4*)&v_sh[par][s][base];
        unsigned long long A10 = 0ull, A11 = 0ull, A20 = 0ull, A21 = 0ull;
        float B1a = -FLT_MAX, B1b = -FLT_MAX, B2a = -FLT_MAX, B2b = -FLT_MAX;
#pragma unroll
        for (int jj = 0; jj < 6; jj++) {
            ulonglong2 e2p = ep[jj];     // e[4jj..4jj+3] of slice (packed pairs)
            float4 v4 = vp[jj];          // v[4jj..4jj+3] of slice
            F32X2_FMA(A10, e2p.x, Ms2a[2 * jj],     A10);
            F32X2_FMA(A11, e2p.y, Ms2a[2 * jj + 1], A11);
            F32X2_FMA(A20, e2p.x, Ms2b[2 * jj],     A20);
            F32X2_FMA(A21, e2p.y, Ms2b[2 * jj + 1], A21);
            B1a = fmaxf(B1a, v4.x + tsa[4 * jj + 0]);
            B1b = fmaxf(B1b, v4.y + tsa[4 * jj + 1]);
            B1a = fmaxf(B1a, v4.z + tsa[4 * jj + 2]);
            B1b = fmaxf(B1b, v4.w + tsa[4 * jj + 3]);
            B2a = fmaxf(B2a, v4.x + tsb[4 * jj + 0]);
            B2b = fmaxf(B2b, v4.y + tsb[4 * jj + 1]);
            B2a = fmaxf(B2a, v4.z + tsb[4 * jj + 2]);
            B2b = fmaxf(B2b, v4.w + tsb[4 * jj + 3]);
        }
        float x0, x1, x2, x3;
        F32X2_UNPACK(x0, x1, A10); F32X2_UNPACK(x2, x3, A11);
        float acc1 = (x0 + x1) + (x2 + x3);
        F32X2_UNPACK(x0, x1, A20); F32X2_UNPACK(x2, x3, A21);
        float acc2 = (x0 + x1) + (x2 + x3);
        float best1 = fmaxf(B1a, B1b);
        float best2 = fmaxf(B2a, B2b);
        // partner combine (lane^1, same warp; executed by all lanes)
        acc1 += __shfl_xor_sync(0xFFFFFFFFu, acc1, 1);
        acc2 += __shfl_xor_sync(0xFFFFFFFFu, acc2, 1);
        best1 = fmaxf(best1, __shfl_xor_sync(0xFFFFFFFFu, best1, 1));
        best2 = fmaxf(best2, __shfl_xor_sync(0xFFFFFFFFu, best2, 1));

        if (h == 0) {
            a1s = e1c + m + __logf(acc1);   // -inf on START row: harmless
            a2s = e2c + m + __logf(acc2);
            v1s = best1 + e1c;
            v2s = best2 + e2c;
            e1c = e1n; e2c = e2n;
            if ((t & 3) == 3) {
                // exact rescale: m += log(max e); e_sh[par] still valid (its
                // next overwrite at t+2 is gated behind t+1's barrier).
                float mx = -FLT_MAX;
#pragma unroll
                for (int p0 = 0; p0 < KK; p0 += 4) {
                    float4 e4 = *reinterpret_cast<const float4*>(&e_sh[par][s][p0]);
                    mx = fmaxf(mx, fmaxf(fmaxf(e4.x, e4.y), fmaxf(e4.z, e4.w)));
                }
                m = m + __logf(mx);
            } else {
                m += 12.f;  // safe bound on per-step alpha growth
            }
        }
    }

    // ---- epilogue: logZ, path_score, best_last, gold reduce ----
    asm volatile("bar.sync %0, 96;" :: "r"(barid));
    if (h == 0) {
        float t1 = trans_sh[TAG_STOP * 49 + nx1];
        float t2 = trans_sh[TAG_STOP * 49 + nx2];
        e_sh[0][s][nx1] = a1s + t1;
        e_sh[0][s][nx2] = a2s + t2;
        v_sh[0][s][nx1] = v1s + t1;
        v_sh[0][s][nx2] = v2s + t2;
        e_sh[1][s][i] = gold;    // 24 partial golds per batch
    }
    asm volatile("bar.sync %0, 96;" :: "r"(barid));
    if (q == 0) {
        float mx = -FLT_MAX;
        for (int k = 0; k < KK; k++) mx = fmaxf(mx, e_sh[0][s][k]);
        float sum = 0.f;
        for (int k = 0; k < KK; k++) sum += __expf(e_sh[0][s][k] - mx);
        float logZ = mx + __logf(sum);

        float gsum = 0.f;
        for (int k = 0; k < 24; k++) gsum += e_sh[1][s][k];
        gsum += trans_sh[TAG_STOP * 49 + tag_sh[s][TT - 1]];
        out[b] = logZ - gsum;                      // nll

        float bv = -FLT_MAX;
        int bi = 0;
        for (int k = 0; k < KK; k++) {
            float tv = v_sh[0][s][k];
            if (tv > bv) { bv = tv; bi = k; }      // first-max
        }
        out[BB + b] = bv;                          // path_score
        g_bestlast[b] = bi;
    }
}

// ============================================================
// Backtrack (R5 proven version): one warp per batch. Recomputes
// bp_t[cur] = first-argmax_p (v_t[p] + trans[cur, p]) along the chosen
// path only. Bit-exact: identical FADD inputs; first-max via
// order-preserving int keys + redux.max + ballot/ffs (lowest index wins).
// v rows prefetched 8-deep (loads are cur-independent).
// ============================================================
__global__ void __launch_bounds__(256)
backtrack_kernel(const float* __restrict__ trans, float* __restrict__ out) {
    __shared__ float trans_sh[KK * 49];
    __shared__ float path_sh[8][TT];

    int tid = threadIdx.x;
    int w = tid >> 5, l = tid & 31;
    int b = blockIdx.x * 8 + w;

    for (int x = tid; x < KK * KK; x += 256) {
        int rr = x / KK, cc = x - rr * KK;
        float tv = trans[x];
        if (rr == TAG_START || cc == TAG_STOP) tv = NEGV;
        trans_sh[rr * 49 + cc] = tv;
    }
    __syncthreads();

    const float* vbase = g_v + (size_t)b * TT * KK;
    bool two = (l < 16);     // lanes 0..15 also own p = l+32

    float ca[8], cb[8], na[8], nb2[8];
#pragma unroll
    for (int x = 0; x < 8; x++) {
        int t = 511 - x;
        ca[x] = __ldg(&vbase[(size_t)t * KK + l]);
        nb2[x] = 0.f;
        cb[x] = two ? __ldg(&vbase[(size_t)t * KK + l + 32]) : 0.f;
    }

    int cur = g_bestlast[b];

    for (int c = 0; c < 64; c++) {
        int tb = 511 - c * 8;
        if (c < 63) {
#pragma unroll
            for (int x = 0; x < 8; x++) {
                int t = tb - 8 - x;
                na[x] = __ldg(&vbase[(size_t)t * KK + l]);
                nb2[x] = two ? __ldg(&vbase[(size_t)t * KK + l + 32]) : 0.f;
            }
        }
#pragma unroll
        for (int x = 0; x < 8; x++) {
            int t = tb - x;
            if (l == 0) path_sh[w][t] = (float)cur;
            float sa = ca[x] + trans_sh[cur * 49 + l];
            float sl = sa;
            int pl = l;
            if (two) {
                float sb = cb[x] + trans_sh[cur * 49 + l + 32];
                if (sb > sa) { sl = sb; pl = l + 32; }   // strict: lower idx wins tie
            }
            int u = __float_as_int(sl);
            int key = u ^ ((u >> 31) & 0x7FFFFFFF);      // order-preserving int key
            int bk;
            asm("redux.sync.max.s32 %0, %1, 0xffffffff;" : "=r"(bk) : "r"(key));
            unsigned m0 = __ballot_sync(0xFFFFFFFFu, (key == bk) && (pl < 32));
            unsigned m1 = __ballot_sync(0xFFFFFFFFu, (key == bk));
            cur = m0 ? (__ffs(m0) - 1) : (__ffs(m1) - 1 + 32);
        }
        if (c < 63) {
#pragma unroll
            for (int x = 0; x < 8; x++) { ca[x] = na[x]; cb[x] = nb2[x]; }
        }
    }

    __syncwarp();
    float* dst = out + 2 * BB + (size_t)b * TT;
    for (int t = l; t < TT; t += 32)
        dst[t] = path_sh[w][t];
}

// ============================================================
extern "C" void kernel_launch(void* const* d_in, const int* in_sizes, int n_in,
                              void* d_out, int out_size) {
    const float* feats = (const float*)d_in[0];
    const float* trans = (const float*)d_in[1];
    const int*   tags  = (const int*)d_in[2];
    float* out = (float*)d_out;

    crf_main_kernel<<<BB / NBAT, MAIN_THREADS>>>(feats, trans, tags, out);
    backtrack_kernel<<<BB / 8, 256>>>(trans, out);
}

// round 17
// speedup vs baseline: 1.1545x; 1.1545x over previous
#include <cuda_runtime.h>
#include <math.h>
#include <float.h>

#define BB 1024
#define TT 512
#define KK 48
#define NEGV (-10000.0f)
#define TAG_START 46
#define TAG_STOP 47
#define NBAT 4                      // batches per CTA (2 groups x 2 batches)
#define MAIN_THREADS 192            // 2 groups x 96 threads

// ---- device scratch (no allocations allowed) ----
__device__ int   g_bestlast[BB];
__device__ float g_v[BB * TT * KK];   // per-step Viterbi value vectors (100 MB)

// f32x2 packed helpers (sm_103a; add/mul/fma only — no packed max exists)
#define F32X2_FMA(d, a, b, c) \
    asm("fma.rn.f32x2 %0, %1, %2, %3;" : "=l"(d) : "l"(a), "l"(b), "l"(c))
#define F32X2_ADD(d, a, b) \
    asm("add.rn.f32x2 %0, %1, %2;" : "=l"(d) : "l"(a), "l"(b))
#define F32X2_UNPACK(lo, hi, x) \
    asm("mov.b64 {%0, %1}, %2;" : "=f"(lo), "=f"(hi) : "l"(x))
#define F32X2_PACK(d, lo, hi) \
    asm("mov.b64 %0, {%1, %2};" : "=l"(d) : "f"(lo), "f"(hi))

// ============================================================
// Fused kernel (R12 baseline + register-resident renorm max):
// BATCH-PAIR INTERLEAVING — each 96-thread group (3 aligned warps) owns
// two batches A,B: store both batches' e/v -> ONE named barrier ->
// compute both (two independent streams per warp).
// Renorm max is now computed from the e values ALREADY loaded in the
// FMA loop (guarded by the uniform (t&3)==3 predicate) + partner shfl —
// removes the 24-LDS.128 renorm burst. e>=0 so 0-init is an exact
// lower bound; max is order-free => numerics bit-identical to R12.
// tid%96 = nx*2 + h : nx = next tag, h = prev half [24h, 24h+24).
// ============================================================
__global__ void __launch_bounds__(MAIN_THREADS, 2)
crf_main_kernel(const float* __restrict__ feats,
                const float* __restrict__ trans,
                const int* __restrict__ tags,
                float* __restrict__ out) {
    __shared__ float trans_sh[KK * 49];                    // masked, pitch 49
    __shared__ __align__(16) float e_sh[2][2][2][KK];      // [par][grp][ab][KK]
    __shared__ __align__(16) float v_sh[2][2][2][KK];
    __shared__ int tag_sh[NBAT][TT];

    int tid = threadIdx.x;
    int grp = tid / 96;          // group = 3 aligned warps
    int r   = tid - grp * 96;
    int nx  = r >> 1;
    int h   = r & 1;
    int base = h * 24;
    int bA  = blockIdx.x * NBAT + grp * 2;
    int bB  = bA + 1;
    int barid = grp + 1;         // named barrier per group (ids 1..2)

    // masked transitions: trans[next, prev]; never INTO start, never OUT of stop
    for (int i = tid; i < KK * KK; i += MAIN_THREADS) {
        int rr = i / KK, cc = i - rr * KK;
        float tv = trans[i];
        if (rr == TAG_START || cc == TAG_STOP) tv = NEGV;
        trans_sh[rr * 49 + cc] = tv;
    }
    for (int i = tid; i < NBAT * TT; i += MAIN_THREADS)
        ((int*)tag_sh)[i] = tags[(size_t)blockIdx.x * NBAT * TT + i];
    __syncthreads();

    // packed register slices of this next-row (24 prevs -> 12 f32x2); shared by A and B
    unsigned long long Ms2[12], ts2[12];
#pragma unroll
    for (int j = 0; j < 12; j++) {
        float t0 = trans_sh[nx * 49 + base + 2 * j];
        float t1 = trans_sh[nx * 49 + base + 2 * j + 1];
        float M0 = (t0 <= -9000.f) ? 0.f : __expf(t0);
        float M1 = (t1 <= -9000.f) ? 0.f : __expf(t1);
        F32X2_PACK(ts2[j], t0, t1);
        F32X2_PACK(Ms2[j], M0, M1);
    }

    float aA = (nx == TAG_START) ? 0.f : NEGV, aB = aA;
    float vA = aA, vB = aA;
    float mA = 0.f, mB = 0.f;
    float goldA = 0.f, goldB = 0.f;
    int ptA = TAG_START, ptB = TAG_START;

    const float* fpA = feats + (size_t)bA * TT * KK + nx;
    const float* fpB = feats + (size_t)bB * TT * KK + nx;
    float emitA = fpA[0], emitB = fpB[0];
    float* voutA = g_v + (size_t)bA * TT * KK + nx;
    float* voutB = g_v + (size_t)bB * TT * KK + nx;

    for (int t = 0; t < TT; t++) {
        int par = t & 1;
        bool ren = ((t & 3) == 3);     // renorm step (uniform)
        float emitA_n = (t + 1 < TT) ? fpA[(size_t)(t + 1) * KK] : 0.f;
        float emitB_n = (t + 1 < TT) ? fpB[(size_t)(t + 1) * KK] : 0.f;

        if (h == 0) {
            e_sh[par][grp][0][nx] = __expf(aA - mA);
            v_sh[par][grp][0][nx] = vA;
            voutA[(size_t)t * KK] = vA;
            e_sh[par][grp][1][nx] = __expf(aB - mB);
            v_sh[par][grp][1][nx] = vB;
            voutB[(size_t)t * KK] = vB;
        }
        asm volatile("bar.sync %0, 96;" :: "r"(barid));   // ONE barrier for both

        // gold: one (nx==tag, h==0) thread per batch per step
        int tgA = tag_sh[grp * 2 + 0][t];
        int tgB = tag_sh[grp * 2 + 1][t];
        if (h == 0 && nx == tgA) goldA += emitA + trans_sh[tgA * 49 + ptA];
        if (h == 0 && nx == tgB) goldB += emitB + trans_sh[tgB * 49 + ptB];
        ptA = tgA; ptB = tgB;

        // ---- compute A and B: two independent streams (ILP) ----
        const ulonglong2* epA = (const ulonglong2*)&e_sh[par][grp][0][base];
        const ulonglong2* vpA = (const ulonglong2*)&v_sh[par][grp][0][base];
        const ulonglong2* epB = (const ulonglong2*)&e_sh[par][grp][1][base];
        const ulonglong2* vpB = (const ulonglong2*)&v_sh[par][grp][1][base];
        unsigned long long accA0 = 0ull, accA1 = 0ull, accB0 = 0ull, accB1 = 0ull;
        float bA0 = -FLT_MAX, bA1 = -FLT_MAX, bB0 = -FLT_MAX, bB1 = -FLT_MAX;
        float lmA = 0.f, lmB = 0.f;    // local renorm max (e >= 0)
#pragma unroll
        for (int j = 0; j < 6; j++) {
            ulonglong2 eA2 = epA[j], vA2 = vpA[j];
            ulonglong2 eB2 = epB[j], vB2 = vpB[j];
            F32X2_FMA(accA0, eA2.x, Ms2[2 * j], accA0);
            F32X2_FMA(accA1, eA2.y, Ms2[2 * j + 1], accA1);
            F32X2_FMA(accB0, eB2.x, Ms2[2 * j], accB0);
            F32X2_FMA(accB1, eB2.y, Ms2[2 * j + 1], accB1);
            if (ren) {   // register-resident renorm max (replaces LDS re-read)
                float u0, u1, u2, u3;
                F32X2_UNPACK(u0, u1, eA2.x); F32X2_UNPACK(u2, u3, eA2.y);
                lmA = fmaxf(lmA, fmaxf(fmaxf(u0, u1), fmaxf(u2, u3)));
                F32X2_UNPACK(u0, u1, eB2.x); F32X2_UNPACK(u2, u3, eB2.y);
                lmB = fmaxf(lmB, fmaxf(fmaxf(u0, u1), fmaxf(u2, u3)));
            }
            unsigned long long sA01, sA23, sB01, sB23;
            F32X2_ADD(sA01, vA2.x, ts2[2 * j]);
            F32X2_ADD(sA23, vA2.y, ts2[2 * j + 1]);
            F32X2_ADD(sB01, vB2.x, ts2[2 * j]);
            F32X2_ADD(sB23, vB2.y, ts2[2 * j + 1]);
            float s0, s1, s2, s3;
            F32X2_UNPACK(s0, s1, sA01);
            F32X2_UNPACK(s2, s3, sA23);
            bA0 = fmaxf(bA0, s0); bA1 = fmaxf(bA1, s1);
            bA0 = fmaxf(bA0, s2); bA1 = fmaxf(bA1, s3);
            F32X2_UNPACK(s0, s1, sB01);
            F32X2_UNPACK(s2, s3, sB23);
            bB0 = fmaxf(bB0, s0); bB1 = fmaxf(bB1, s1);
            bB0 = fmaxf(bB0, s2); bB1 = fmaxf(bB1, s3);
        }
        float x0, x1, x2, x3;
        F32X2_UNPACK(x0, x1, accA0);
        F32X2_UNPACK(x2, x3, accA1);
        float accA = (x0 + x1) + (x2 + x3);
        F32X2_UNPACK(x0, x1, accB0);
        F32X2_UNPACK(x2, x3, accB1);
        float accB = (x0 + x1) + (x2 + x3);
        float bestA = fmaxf(bA0, bA1);
        float bestB = fmaxf(bB0, bB1);
        // partner combine (lane^1, same warp)
        accA += __shfl_xor_sync(0xFFFFFFFFu, accA, 1);
        accB += __shfl_xor_sync(0xFFFFFFFFu, accB, 1);
        bestA = fmaxf(bestA, __shfl_xor_sync(0xFFFFFFFFu, bestA, 1));
        bestB = fmaxf(bestB, __shfl_xor_sync(0xFFFFFFFFu, bestB, 1));

        aA = emitA + mA + __logf(accA);   // -inf on START row: harmless
        aB = emitB + mB + __logf(accB);
        vA = bestA + emitA;
        vB = bestB + emitB;
        emitA = emitA_n;
        emitB = emitB_n;

        if (ren) {
            // exact rescale: m += log(max over all 48 loop-top e), computed
            // from registers + partner shfl (same 48 values as the old smem
            // re-read; max is order-free => identical result).
            float mxA = fmaxf(lmA, __shfl_xor_sync(0xFFFFFFFFu, lmA, 1));
            float mxB = fmaxf(lmB, __shfl_xor_sync(0xFFFFFFFFu, lmB, 1));
            mA = mA + __logf(mxA);
            mB = mB + __logf(mxB);
        } else {
            mA += 12.f;  // safe bound on per-step alpha growth
            mB += 12.f;
        }
    }

    // ---- epilogue: logZ, path_score, best_last, gold reduce (both batches) ----
    asm volatile("bar.sync %0, 96;" :: "r"(barid));
    if (h == 0) {
        float tstop = trans_sh[TAG_STOP * 49 + nx];
        e_sh[0][grp][0][nx] = aA + tstop;
        e_sh[0][grp][1][nx] = aB + tstop;
        v_sh[0][grp][0][nx] = vA + tstop;
        v_sh[0][grp][1][nx] = vB + tstop;
        e_sh[1][grp][0][nx] = goldA;
        e_sh[1][grp][1][nx] = goldB;
    }
    asm volatile("bar.sync %0, 96;" :: "r"(barid));
    if (r == 0) {
#pragma unroll
        for (int ab = 0; ab < 2; ab++) {
            int b = bA + ab;
            float mx = -FLT_MAX;
            for (int k = 0; k < KK; k++) mx = fmaxf(mx, e_sh[0][grp][ab][k]);
            float s = 0.f;
            for (int k = 0; k < KK; k++) s += __expf(e_sh[0][grp][ab][k] - mx);
            float logZ = mx + __logf(s);

            float gsum = 0.f;
            for (int k = 0; k < KK; k++) gsum += e_sh[1][grp][ab][k];
            gsum += trans_sh[TAG_STOP * 49 + tag_sh[grp * 2 + ab][TT - 1]];
            out[b] = logZ - gsum;                      // nll

            float bv = -FLT_MAX;
            int bi = 0;
            for (int k = 0; k < KK; k++) {
                float tv = v_sh[0][grp][ab][k];
                if (tv > bv) { bv = tv; bi = k; }      // first-max
            }
            out[BB + b] = bv;                          // path_score
            g_bestlast[b] = bi;
        }
    }
}

// ============================================================
// Backtrack (R5 proven version): one warp per batch. Recomputes
// bp_t[cur] = first-argmax_p (v_t[p] + trans[cur, p]) along the chosen
// path only. Bit-exact: identical FADD inputs; first-max via
// order-preserving int keys + redux.max + ballot/ffs (lowest index wins).
// v rows prefetched 8-deep (loads are cur-independent).
// ============================================================
__global__ void __launch_bounds__(256)
backtrack_kernel(const float* __restrict__ trans, float* __restrict__ out) {
    __shared__ float trans_sh[KK * 49];
    __shared__ float path_sh[8][TT];

    int tid = threadIdx.x;
    int w = tid >> 5, l = tid & 31;
    int b = blockIdx.x * 8 + w;

    for (int i = tid; i < KK * KK; i += 256) {
        int rr = i / KK, cc = i - rr * KK;
        float tv = trans[i];
        if (rr == TAG_START || cc == TAG_STOP) tv = NEGV;
        trans_sh[rr * 49 + cc] = tv;
    }
    __syncthreads();

    const float* vbase = g_v + (size_t)b * TT * KK;
    bool two = (l < 16);     // lanes 0..15 also own p = l+32

    float ca[8], cb[8], na[8], nb2[8];
#pragma unroll
    for (int i = 0; i < 8; i++) {
        int t = 511 - i;
        ca[i] = __ldg(&vbase[(size_t)t * KK + l]);
        nb2[i] = 0.f;
        cb[i] = two ? __ldg(&vbase[(size_t)t * KK + l + 32]) : 0.f;
    }

    int cur = g_bestlast[b];

    for (int c = 0; c < 64; c++) {
        int tb = 511 - c * 8;
        if (c < 63) {
#pragma unroll
            for (int i = 0; i < 8; i++) {
                int t = tb - 8 - i;
                na[i] = __ldg(&vbase[(size_t)t * KK + l]);
                nb2[i] = two ? __ldg(&vbase[(size_t)t * KK + l + 32]) : 0.f;
            }
        }
#pragma unroll
        for (int i = 0; i < 8; i++) {
            int t = tb - i;
            if (l == 0) path_sh[w][t] = (float)cur;
            float sa = ca[i] + trans_sh[cur * 49 + l];
            float sl = sa;
            int pl = l;
            if (two) {
                float sb = cb[i] + trans_sh[cur * 49 + l + 32];
                if (sb > sa) { sl = sb; pl = l + 32; }   // strict: lower idx wins tie
            }
            int u = __float_as_int(sl);
            int key = u ^ ((u >> 31) & 0x7FFFFFFF);      // order-preserving int key
            int bk;
            asm("redux.sync.max.s32 %0, %1, 0xffffffff;" : "=r"(bk) : "r"(key));
            unsigned m0 = __ballot_sync(0xFFFFFFFFu, (key == bk) && (pl < 32));
            unsigned m1 = __ballot_sync(0xFFFFFFFFu, (key == bk));
            cur = m0 ? (__ffs(m0) - 1) : (__ffs(m1) - 1 + 32);
        }
        if (c < 63) {
#pragma unroll
            for (int i = 0; i < 8; i++) { ca[i] = na[i]; cb[i] = nb2[i]; }
        }
    }

    __syncwarp();
    float* dst = out + 2 * BB + (size_t)b * TT;
    for (int t = l; t < TT; t += 32)
        dst[t] = path_sh[w][t];
}

// ============================================================
extern "C" void kernel_launch(void* const* d_in, const int* in_sizes, int n_in,
                              void* d_out, int out_size) {
    const float* feats = (const float*)d_in[0];
    const float* trans = (const float*)d_in[1];
    const int*   tags  = (const int*)d_in[2];
    float* out = (float*)d_out;

    crf_main_kernel<<<BB / NBAT, MAIN_THREADS>>>(feats, trans, tags, out);
    backtrack_kernel<<<BB / 8, 256>>>(trans, out);
}